// round 14
// baseline (speedup 1.0000x reference)
#include <cuda_runtime.h>
#include <cuda_bf16.h>
#include <cuda_fp16.h>
#include <stdint.h>

#define BHN 16
#define LEN 2048
#define DIM 64
#define RN  4
#define NB2 16
#define CH  128
#define NK  256
#define XSTR 72    // k_scores staged row stride (bf16)
#define VSTR 264   // k_av vT row stride (fp16 elements)

typedef unsigned long long ull;

// ---------------- scratch (device globals; allocation-free) ----------------
__device__ float    g_qn  [BHN][LEN][DIM];
__device__ float    g_rmn [BHN][DIM][64];
__device__ int      g_hash[BHN][RN][LEN];
__device__ int      g_hidx[BHN][RN][LEN];
__device__ int      g_oidx[BHN][RN][LEN];
__device__ float    g_sc  [BHN][RN][LEN][NK];   // adjusted scores (read-only after K3)
__device__ __half   g_ph  [BHN][RN][LEN][NK];   // p as fp16 (64 MB)
__device__ float    g_attn[BHN][RN][LEN][DIM];

__constant__ float c_log4[4] = {0.0f, 0.6931471805599453f, 1.0986122886681098f, 1.3862943611198906f};

// fast exp on the FMA pipe — R2's exact version
__device__ __forceinline__ float fexp(float x) {
    x = fmaxf(x, -87.0f);
    float t = fmaf(x, 1.4426950408889634f, 12582912.0f);
    int n = __float_as_int(t) - 0x4B400000;
    float fi = t - 12582912.0f;
    float z = fmaf(fi, -0.6931471805599453f, x);
    float p = 8.3333337e-3f;
    p = fmaf(p, z, 4.1666668e-2f);
    p = fmaf(p, z, 0.16666667f);
    p = fmaf(p, z, 0.5f);
    p = fmaf(p, z, 1.0f);
    p = fmaf(p, z, 1.0f);
    return p * __int_as_float((n + 127) << 23);
}

// ---------------- mma.sync m16n8k16 (bf16 and f16 variants) ----------------
__device__ __forceinline__ void mma_bf16(float* c, const uint32_t* a, uint32_t b0, uint32_t b1) {
    asm volatile(
        "mma.sync.aligned.m16n8k16.row.col.f32.bf16.bf16.f32 "
        "{%0,%1,%2,%3}, {%4,%5,%6,%7}, {%8,%9}, {%0,%1,%2,%3};"
        : "+f"(c[0]), "+f"(c[1]), "+f"(c[2]), "+f"(c[3])
        : "r"(a[0]), "r"(a[1]), "r"(a[2]), "r"(a[3]), "r"(b0), "r"(b1));
}
__device__ __forceinline__ void mma_f16(float* c, const uint32_t* a, uint32_t b0, uint32_t b1) {
    asm volatile(
        "mma.sync.aligned.m16n8k16.row.col.f32.f16.f16.f32 "
        "{%0,%1,%2,%3}, {%4,%5,%6,%7}, {%8,%9}, {%0,%1,%2,%3};"
        : "+f"(c[0]), "+f"(c[1]), "+f"(c[2]), "+f"(c[3])
        : "r"(a[0]), "r"(a[1]), "r"(a[2]), "r"(a[3]), "r"(b0), "r"(b1));
}

// split float2 -> packed bf16 hi (x) and lo (y); low half = .x
__device__ __forceinline__ uint2 split2(float2 f) {
    __nv_bfloat16 h0 = __float2bfloat16(f.x);
    __nv_bfloat16 h1 = __float2bfloat16(f.y);
    __nv_bfloat16 l0 = __float2bfloat16(f.x - __bfloat162float(h0));
    __nv_bfloat16 l1 = __float2bfloat16(f.y - __bfloat162float(h1));
    uint2 r;
    r.x = ((uint32_t)__bfloat16_as_ushort(h1) << 16) | __bfloat16_as_ushort(h0);
    r.y = ((uint32_t)__bfloat16_as_ushort(l1) << 16) | __bfloat16_as_ushort(l0);
    return r;
}
// split float2 -> packed fp16 hi (x) and lo (y); low half = .x
__device__ __forceinline__ uint2 split2h(float2 f) {
    __half h0 = __float2half_rn(f.x);
    __half h1 = __float2half_rn(f.y);
    __half l0 = __float2half_rn(f.x - __half2float(h0));
    __half l1 = __float2half_rn(f.y - __half2float(h1));
    uint2 r;
    r.x = ((uint32_t)__half_as_ushort(h1) << 16) | __half_as_ushort(h0);
    r.y = ((uint32_t)__half_as_ushort(l1) << 16) | __half_as_ushort(l0);
    return r;
}
__device__ __forceinline__ uint32_t pack2h(float a, float b) {
    __half2 h = __floats2half2_rn(a, b);   // .x = a (low)
    return *(uint32_t*)&h;
}

// ---------------- K0: normalize rand_matrix columns ----------------
__global__ void k_rmn(const float* __restrict__ rm) {
    int b = blockIdx.x;
    int j = threadIdx.x;
    float s = 0.f;
    for (int d = 0; d < DIM; d++) {
        float v = rm[(size_t)(b * DIM + d) * 64 + j];
        s += v * v;
    }
    float inv = rsqrtf(s);
    for (int d = 0; d < DIM; d++)
        g_rmn[b][d][j] = rm[(size_t)(b * DIM + d) * 64 + j] * inv;
}

// ---------------- K1: normalize q + hashes ----------------
__global__ void __launch_bounds__(128) k_hash(const float* __restrict__ q) {
    int b = blockIdx.y;
    __shared__ float s_rm[DIM * 64];
    int tid = threadIdx.x;
    const float4* rsrc = (const float4*)&g_rmn[b][0][0];
    for (int t = tid; t < DIM * 64 / 4; t += 128) ((float4*)s_rm)[t] = rsrc[t];
    __syncthreads();

    int l = blockIdx.x * 128 + tid;
    float qv[DIM];
    const float4* qp = (const float4*)&q[((size_t)b * LEN + l) * DIM];
#pragma unroll
    for (int t = 0; t < 16; t++) {
        float4 v = qp[t];
        qv[4 * t] = v.x; qv[4 * t + 1] = v.y; qv[4 * t + 2] = v.z; qv[4 * t + 3] = v.w;
    }
    float ss = 0.f;
#pragma unroll
    for (int d = 0; d < DIM; d++) ss += qv[d] * qv[d];
    float inv = rsqrtf(ss);
#pragma unroll
    for (int d = 0; d < DIM; d++) qv[d] *= inv;
    float4* qd = (float4*)&g_qn[b][l][0];
#pragma unroll
    for (int t = 0; t < 16; t++)
        qd[t] = make_float4(qv[4 * t], qv[4 * t + 1], qv[4 * t + 2], qv[4 * t + 3]);

    for (int r = 0; r < RN; r++) {
        float bp = -1e30f, bn = -1e30f;
        int bpi = 0, bni = 0;
        for (int k = 0; k < 16; k++) {
            float acc = 0.f;
#pragma unroll
            for (int d = 0; d < DIM; d++) acc += qv[d] * s_rm[d * 64 + r * 16 + k];
            if (acc > bp)  { bp = acc;  bpi = k; }
            if (-acc > bn) { bn = -acc; bni = k; }
        }
        g_hash[b][r][l] = (bn > bp) ? (16 + bni) : bpi;
    }
}

// ---------------- K2: stable counting sort per (b,r) ----------------
__global__ void __launch_bounds__(256) k_sort() {
    int b = blockIdx.x >> 2, r = blockIdx.x & 3;
    __shared__ int hist[32][257];
    __shared__ int base[32];
    int t = threadIdx.x;
#pragma unroll
    for (int v = 0; v < 32; v++) hist[v][t] = 0;
    __syncthreads();
    int h[8];
#pragma unroll
    for (int e = 0; e < 8; e++) {
        h[e] = g_hash[b][r][t * 8 + e];
        hist[h[e]][t]++;
    }
    __syncthreads();
    if (t < 32) {
        int run = 0;
        for (int i = 0; i < 256; i++) { int x = hist[t][i]; hist[t][i] = run; run += x; }
        base[t] = run;
    }
    __syncthreads();
    if (t == 0) {
        int run = 0;
        for (int v = 0; v < 32; v++) { int x = base[v]; base[v] = run; run += x; }
    }
    __syncthreads();
#pragma unroll
    for (int e = 0; e < 8; e++) {
        int l = t * 8 + e, v = h[e];
        int off = hist[v][t];
        hist[v][t] = off + 1;
        int pos = base[v] + off;
        g_hidx[b][r][pos] = l;
        g_oidx[b][r][l] = pos;
    }
}

// ---------------- K3: bf16-split mma.sync score GEMM (R13 verbatim) ----------------
#define SM3_TOTAL (4096 + 2 * NK * XSTR * 2)

__global__ void __launch_bounds__(1024) k_scores() {
    int n = blockIdx.x, r = blockIdx.y, b = blockIdx.z;
    extern __shared__ char sm3[];
    int2* kmeta = (int2*)sm3;
    __nv_bfloat16* xh = (__nv_bfloat16*)(sm3 + 4096);
    __nv_bfloat16* xl = (__nv_bfloat16*)(sm3 + 4096 + NK * XSTR * 2);
    int tid = threadIdx.x;
    int prevbase = ((n + NB2 - 1) & (NB2 - 1)) * CH;

    for (int j = tid; j < NK; j += 1024) {
        int keypos = (j < CH) ? (prevbase + j) : (n * CH + j - CH);
        int ki = g_hidx[b][r][keypos];
        int kh = g_hash[b][r][ki];
        int pc = 0;
#pragma unroll
        for (int rr = 0; rr < RN; rr++)
            pc |= ((g_oidx[b][rr][ki] >> 7) & 15) << (8 * rr);
        kmeta[j] = make_int2((kh << 16) | ki, pc);
    }
    __syncthreads();

    for (int t = tid; t < NK * 16; t += 1024) {
        int row = t >> 4, cg = t & 15;
        int ki = kmeta[row].x & 0xFFFF;
        float4 v = *(const float4*)&g_qn[b][ki][cg * 4];
        uint2 p0 = split2(make_float2(v.x, v.y));
        uint2 p1 = split2(make_float2(v.z, v.w));
        *(uint2*)&xh[row * XSTR + cg * 4] = make_uint2(p0.x, p1.x);
        *(uint2*)&xl[row * XSTR + cg * 4] = make_uint2(p0.y, p1.y);
    }
    __syncthreads();

    int wid = tid >> 5, lane = tid & 31;
    int wm = wid >> 2, wn = wid & 3;
    int i0 = wm * 16, j0 = wn * 64;
    int g = lane >> 2, t4 = lane & 3;

    float acc[8][4];
#pragma unroll
    for (int nt = 0; nt < 8; nt++)
#pragma unroll
        for (int c = 0; c < 4; c++) acc[nt][c] = 0.f;

    const __nv_bfloat16* Ah = xh + (CH + i0) * XSTR;
    const __nv_bfloat16* Al = xl + (CH + i0) * XSTR;
#pragma unroll
    for (int ks = 0; ks < 4; ks++) {
        int k0 = ks * 16 + 2 * t4;
        uint32_t ah[4], al[4];
        ah[0] = *(const uint32_t*)&Ah[g * XSTR + k0];
        ah[1] = *(const uint32_t*)&Ah[(g + 8) * XSTR + k0];
        ah[2] = *(const uint32_t*)&Ah[g * XSTR + k0 + 8];
        ah[3] = *(const uint32_t*)&Ah[(g + 8) * XSTR + k0 + 8];
        al[0] = *(const uint32_t*)&Al[g * XSTR + k0];
        al[1] = *(const uint32_t*)&Al[(g + 8) * XSTR + k0];
        al[2] = *(const uint32_t*)&Al[g * XSTR + k0 + 8];
        al[3] = *(const uint32_t*)&Al[(g + 8) * XSTR + k0 + 8];
#pragma unroll
        for (int nt = 0; nt < 8; nt++) {
            int rowb = (j0 + nt * 8 + g) * XSTR + k0;
            uint32_t bh0 = *(const uint32_t*)&xh[rowb];
            uint32_t bh1 = *(const uint32_t*)&xh[rowb + 8];
            uint32_t bl0 = *(const uint32_t*)&xl[rowb];
            uint32_t bl1 = *(const uint32_t*)&xl[rowb + 8];
            mma_bf16(acc[nt], ah, bh0, bh1);
            mma_bf16(acc[nt], ah, bl0, bl1);
            mma_bf16(acc[nt], al, bh0, bh1);
        }
    }

    int ia = i0 + g, ib = i0 + g + 8;
    int2 qa = kmeta[CH + ia], qb = kmeta[CH + ib];
    int qidxa = qa.x & 0xFFFF, qha = qa.x >> 16, npa = qa.y;
    int qidxb = qb.x & 0xFFFF, qhb = qb.x >> 16, npb = qb.y;
    int ppa = ((npa | 0x10101010) - 0x01010101) & 0x0f0f0f0f;
    int ppb = ((npb | 0x10101010) - 0x01010101) & 0x0f0f0f0f;
    float* rowa = &g_sc[b][r][n * CH + ia][0];
    float* rowb = &g_sc[b][r][n * CH + ib][0];
#pragma unroll
    for (int nt = 0; nt < 8; nt++) {
        int j = j0 + nt * 8 + 2 * t4;
        int4 km = *(const int4*)&kmeta[j];
        int kj0 = km.x & 0xFFFF, kh0 = km.x >> 16, kc0 = km.y;
        int kj1 = km.z & 0xFFFF, kh1 = km.z >> 16, kc1 = km.w;
        float o00 = acc[nt][0] * 0.125f, o01 = acc[nt][1] * 0.125f;
        float o10 = acc[nt][2] * 0.125f, o11 = acc[nt][3] * 0.125f;
        if (qidxa == kj0)                      o00 = -100000.0f;
        else if (qidxa < kj0 || qha != kh0)    o00 = -1000000000.0f;
        if (qidxa == kj1)                      o01 = -100000.0f;
        else if (qidxa < kj1 || qha != kh1)    o01 = -1000000000.0f;
        if (qidxb == kj0)                      o10 = -100000.0f;
        else if (qidxb < kj0 || qhb != kh0)    o10 = -1000000000.0f;
        if (qidxb == kj1)                      o11 = -100000.0f;
        else if (qidxb < kj1 || qhb != kh1)    o11 = -1000000000.0f;
        unsigned m;
        m = __vcmpeq4((unsigned)kc0, (unsigned)npa) | __vcmpeq4((unsigned)kc0, (unsigned)ppa);
        o00 -= c_log4[(__popc(m) >> 3) - 1];
        m = __vcmpeq4((unsigned)kc1, (unsigned)npa) | __vcmpeq4((unsigned)kc1, (unsigned)ppa);
        o01 -= c_log4[(__popc(m) >> 3) - 1];
        m = __vcmpeq4((unsigned)kc0, (unsigned)npb) | __vcmpeq4((unsigned)kc0, (unsigned)ppb);
        o10 -= c_log4[(__popc(m) >> 3) - 1];
        m = __vcmpeq4((unsigned)kc1, (unsigned)npb) | __vcmpeq4((unsigned)kc1, (unsigned)ppb);
        o11 -= c_log4[(__popc(m) >> 3) - 1];
        *(float2*)&rowa[j] = make_float2(o00, o01);
        *(float2*)&rowb[j] = make_float2(o10, o11);
    }
}

// ---------------- K4: joint softmax -> fp16 p (g_ph) ----------------
__global__ void __launch_bounds__(512) k_softmax() {
    int b = blockIdx.y;
    int warp = threadIdx.x >> 5, lane = threadIdx.x & 31;
#pragma unroll 1
    for (int it = 0; it < 16; it++) {
        int l = blockIdx.x * 256 + it * 16 + warp;
        int srs[RN];
        float4 adj[RN][2];
        float mx = -3.4e38f;
#pragma unroll
        for (int r = 0; r < RN; r++) {
            srs[r] = g_oidx[b][r][l];
            const float4* srow = (const float4*)&g_sc[b][r][srs[r]][0];
            adj[r][0] = srow[lane];
            adj[r][1] = srow[lane + 32];
#pragma unroll
            for (int h = 0; h < 2; h++) {
                mx = fmaxf(mx, fmaxf(fmaxf(adj[r][h].x, adj[r][h].y),
                                     fmaxf(adj[r][h].z, adj[r][h].w)));
            }
        }
#pragma unroll
        for (int o = 16; o; o >>= 1) mx = fmaxf(mx, __shfl_xor_sync(0xffffffffu, mx, o));
        float sum = 0.f;
#pragma unroll
        for (int r = 0; r < RN; r++)
#pragma unroll
            for (int h = 0; h < 2; h++) {
                adj[r][h].x = fexp(adj[r][h].x - mx);
                adj[r][h].y = fexp(adj[r][h].y - mx);
                adj[r][h].z = fexp(adj[r][h].z - mx);
                adj[r][h].w = fexp(adj[r][h].w - mx);
                sum += adj[r][h].x + adj[r][h].y + adj[r][h].z + adj[r][h].w;
            }
#pragma unroll
        for (int o = 16; o; o >>= 1) sum += __shfl_xor_sync(0xffffffffu, sum, o);
        float inv = 1.0f / sum;
#pragma unroll
        for (int r = 0; r < RN; r++) {
            __half* prow = &g_ph[b][r][srs[r]][0];
#pragma unroll
            for (int h = 0; h < 2; h++) {
                float4 w = adj[r][h];
                uint2 o2;
                o2.x = pack2h(w.x * inv, w.y * inv);
                o2.y = pack2h(w.z * inv, w.w * inv);
                *(uint2*)&prow[h * 128 + 4 * lane] = o2;
            }
        }
    }
}

// ---------------- K5: f16 mma.sync p @ v_sorted (p fp16, v fp16-split), 1024 thr ----------------
#define SM5_TOTAL (2 * 64 * VSTR * 2)   // 2 planes x 64 rows x VSTR fp16 = 67584 B

__global__ void __launch_bounds__(1024) k_av(const float* __restrict__ v) {
    int n = blockIdx.x, r = blockIdx.y, b = blockIdx.z;
    extern __shared__ char sm5[];
    __half* vh = (__half*)sm5;
    __half* vl = vh + 64 * VSTR;
    int tid = threadIdx.x;
    int prevbase = ((n + NB2 - 1) & (NB2 - 1)) * CH;

    // stage vT fp16 hi/lo: row = d, col = j (pairs packed in uint32, low = even j)
    for (int idx = tid; idx < 128 * 16; idx += 1024) {
        int jp = idx & 127, f = idx >> 7;
        int ja = 2 * jp, jb = 2 * jp + 1;
        int kpa = (ja < CH) ? (prevbase + ja) : (n * CH + ja - CH);
        int kpb = (jb < CH) ? (prevbase + jb) : (n * CH + jb - CH);
        int kia = g_hidx[b][r][kpa];
        int kib = g_hidx[b][r][kpb];
        float4 va = *(const float4*)&v[((size_t)b * LEN + kia) * DIM + f * 4];
        float4 vb = *(const float4*)&v[((size_t)b * LEN + kib) * DIM + f * 4];
        float pa[4] = {va.x, va.y, va.z, va.w};
        float pb[4] = {vb.x, vb.y, vb.z, vb.w};
#pragma unroll
        for (int c = 0; c < 4; c++) {
            uint2 s = split2h(make_float2(pa[c], pb[c]));
            *(uint32_t*)&vh[(f * 4 + c) * VSTR + 2 * jp] = s.x;
            *(uint32_t*)&vl[(f * 4 + c) * VSTR + 2 * jp] = s.y;
        }
    }
    __syncthreads();

    int wid = tid >> 5, lane = tid & 31;
    int wm = wid >> 2, wn = wid & 3;     // 8 m-tiles x 4 d-tiles
    int i0 = wm * 16, d0 = wn * 16;
    int g = lane >> 2, t4 = lane & 3;

    float acc[2][4];
#pragma unroll
    for (int nt = 0; nt < 2; nt++)
#pragma unroll
        for (int c = 0; c < 4; c++) acc[nt][c] = 0.f;

    const __half* p0 = &g_ph[b][r][n * CH + i0 + g][0];
    const __half* p8 = &g_ph[b][r][n * CH + i0 + g + 8][0];
#pragma unroll 4
    for (int ks = 0; ks < 16; ks++) {
        int k0 = ks * 16 + 2 * t4;
        uint32_t a[4];
        a[0] = *(const uint32_t*)&p0[k0];
        a[1] = *(const uint32_t*)&p8[k0];
        a[2] = *(const uint32_t*)&p0[k0 + 8];
        a[3] = *(const uint32_t*)&p8[k0 + 8];
#pragma unroll
        for (int nt = 0; nt < 2; nt++) {
            int rowb = (d0 + nt * 8 + g) * VSTR + k0;
            uint32_t bh0 = *(const uint32_t*)&vh[rowb];
            uint32_t bh1 = *(const uint32_t*)&vh[rowb + 8];
            uint32_t bl0 = *(const uint32_t*)&vl[rowb];
            uint32_t bl1 = *(const uint32_t*)&vl[rowb + 8];
            mma_f16(acc[nt], a, bh0, bh1);
            mma_f16(acc[nt], a, bl0, bl1);
        }
    }

    int ia = i0 + g, ib = ia + 8;
#pragma unroll
    for (int nt = 0; nt < 2; nt++) {
        int d = d0 + nt * 8 + 2 * t4;
        *(float2*)&g_attn[b][r][n * CH + ia][d] = make_float2(acc[nt][0], acc[nt][1]);
        *(float2*)&g_attn[b][r][n * CH + ib][d] = make_float2(acc[nt][2], acc[nt][3]);
    }
}

// ---------------- K6: gather rounds back to original order, sum ----------------
__global__ void __launch_bounds__(256) k_out(float* __restrict__ out) {
    int gid = blockIdx.x * 256 + threadIdx.x;
    int dq = gid & 15;
    int l = (gid >> 4) & (LEN - 1);
    int b = gid >> 15;
    float4 s = make_float4(0.f, 0.f, 0.f, 0.f);
#pragma unroll
    for (int r = 0; r < RN; r++) {
        int sIdx = g_oidx[b][r][l];
        float4 a = *(const float4*)&g_attn[b][r][sIdx][dq * 4];
        s.x += a.x; s.y += a.y; s.z += a.z; s.w += a.w;
    }
    *(float4*)&out[((size_t)b * LEN + l) * DIM + dq * 4] = s;
}

// ---------------- launch ----------------
extern "C" void kernel_launch(void* const* d_in, const int* in_sizes, int n_in,
                              void* d_out, int out_size) {
    const float* q  = (const float*)d_in[0];
    const float* v  = (const float*)d_in[1];
    const float* rm = (const float*)d_in[2];
    float* out = (float*)d_out;

    cudaFuncSetAttribute(k_scores, cudaFuncAttributeMaxDynamicSharedMemorySize, SM3_TOTAL);
    cudaFuncSetAttribute(k_av,     cudaFuncAttributeMaxDynamicSharedMemorySize, SM5_TOTAL);

    k_rmn<<<BHN, 64>>>(rm);
    k_hash<<<dim3(LEN / 128, BHN), 128>>>(q);
    k_sort<<<BHN * RN, 256>>>();
    k_scores<<<dim3(NB2, RN, BHN), 1024, SM3_TOTAL>>>();   // launch #3 -> ncu slot
    k_softmax<<<dim3(LEN / 256, BHN), 512>>>();
    k_av<<<dim3(NB2, RN, BHN), 1024, SM5_TOTAL>>>(v);
    k_out<<<(BHN * LEN * 16) / 256, 256>>>(out);
}

// round 15
// speedup vs baseline: 1.0797x; 1.0797x over previous
#include <cuda_runtime.h>
#include <cuda_bf16.h>
#include <cuda_fp16.h>
#include <stdint.h>

#define BHN 16
#define LEN 2048
#define DIM 64
#define RN  4
#define NB2 16
#define CH  128
#define NK  256
#define XSTR 72    // k_scores staged row stride (bf16)
#define VSTR 264   // k_av vT row stride (fp16 elements)

typedef unsigned long long ull;

// ---------------- scratch (device globals; allocation-free) ----------------
__device__ float    g_qn  [BHN][LEN][DIM];
__device__ float    g_rmn [BHN][DIM][64];
__device__ int      g_hash[BHN][RN][LEN];
__device__ int      g_hidx[BHN][RN][LEN];
__device__ int      g_oidx[BHN][RN][LEN];
__device__ float    g_sc  [BHN][RN][LEN][NK];   // adjusted scores (read-only after K3)
// p as fp16 in fragment-unit layout: unit u = (P>>3)*4 + (P&7) holds pairs {P, P+4}
// (P = k-pair index 0..127); unit = 4 fp16 = 8 bytes.
__device__ __align__(16) __half g_ph[BHN][RN][LEN][NK];
__device__ float    g_attn[BHN][RN][LEN][DIM];

__constant__ float c_log4[4] = {0.0f, 0.6931471805599453f, 1.0986122886681098f, 1.3862943611198906f};

// fast exp on the FMA pipe — R2's exact version
__device__ __forceinline__ float fexp(float x) {
    x = fmaxf(x, -87.0f);
    float t = fmaf(x, 1.4426950408889634f, 12582912.0f);
    int n = __float_as_int(t) - 0x4B400000;
    float fi = t - 12582912.0f;
    float z = fmaf(fi, -0.6931471805599453f, x);
    float p = 8.3333337e-3f;
    p = fmaf(p, z, 4.1666668e-2f);
    p = fmaf(p, z, 0.16666667f);
    p = fmaf(p, z, 0.5f);
    p = fmaf(p, z, 1.0f);
    p = fmaf(p, z, 1.0f);
    return p * __int_as_float((n + 127) << 23);
}

// ---------------- mma.sync m16n8k16 (bf16 and f16 variants) ----------------
__device__ __forceinline__ void mma_bf16(float* c, const uint32_t* a, uint32_t b0, uint32_t b1) {
    asm volatile(
        "mma.sync.aligned.m16n8k16.row.col.f32.bf16.bf16.f32 "
        "{%0,%1,%2,%3}, {%4,%5,%6,%7}, {%8,%9}, {%0,%1,%2,%3};"
        : "+f"(c[0]), "+f"(c[1]), "+f"(c[2]), "+f"(c[3])
        : "r"(a[0]), "r"(a[1]), "r"(a[2]), "r"(a[3]), "r"(b0), "r"(b1));
}
__device__ __forceinline__ void mma_f16(float* c, const uint32_t* a, uint32_t b0, uint32_t b1) {
    asm volatile(
        "mma.sync.aligned.m16n8k16.row.col.f32.f16.f16.f32 "
        "{%0,%1,%2,%3}, {%4,%5,%6,%7}, {%8,%9}, {%0,%1,%2,%3};"
        : "+f"(c[0]), "+f"(c[1]), "+f"(c[2]), "+f"(c[3])
        : "r"(a[0]), "r"(a[1]), "r"(a[2]), "r"(a[3]), "r"(b0), "r"(b1));
}

// split float2 -> packed bf16 hi (x) and lo (y); low half = .x
__device__ __forceinline__ uint2 split2(float2 f) {
    __nv_bfloat16 h0 = __float2bfloat16(f.x);
    __nv_bfloat16 h1 = __float2bfloat16(f.y);
    __nv_bfloat16 l0 = __float2bfloat16(f.x - __bfloat162float(h0));
    __nv_bfloat16 l1 = __float2bfloat16(f.y - __bfloat162float(h1));
    uint2 r;
    r.x = ((uint32_t)__bfloat16_as_ushort(h1) << 16) | __bfloat16_as_ushort(h0);
    r.y = ((uint32_t)__bfloat16_as_ushort(l1) << 16) | __bfloat16_as_ushort(l0);
    return r;
}
// split float2 -> packed fp16 hi (x) and lo (y); low half = .x
__device__ __forceinline__ uint2 split2h(float2 f) {
    __half h0 = __float2half_rn(f.x);
    __half h1 = __float2half_rn(f.y);
    __half l0 = __float2half_rn(f.x - __half2float(h0));
    __half l1 = __float2half_rn(f.y - __half2float(h1));
    uint2 r;
    r.x = ((uint32_t)__half_as_ushort(h1) << 16) | __half_as_ushort(h0);
    r.y = ((uint32_t)__half_as_ushort(l1) << 16) | __half_as_ushort(l0);
    return r;
}
__device__ __forceinline__ uint32_t pack2h(float a, float b) {
    __half2 h = __floats2half2_rn(a, b);   // .x = a (low)
    return *(uint32_t*)&h;
}

// ---------------- K0: normalize rand_matrix columns ----------------
__global__ void k_rmn(const float* __restrict__ rm) {
    int b = blockIdx.x;
    int j = threadIdx.x;
    float s = 0.f;
    for (int d = 0; d < DIM; d++) {
        float v = rm[(size_t)(b * DIM + d) * 64 + j];
        s += v * v;
    }
    float inv = rsqrtf(s);
    for (int d = 0; d < DIM; d++)
        g_rmn[b][d][j] = rm[(size_t)(b * DIM + d) * 64 + j] * inv;
}

// ---------------- K1: normalize q + hashes ----------------
__global__ void __launch_bounds__(128) k_hash(const float* __restrict__ q) {
    int b = blockIdx.y;
    __shared__ float s_rm[DIM * 64];
    int tid = threadIdx.x;
    const float4* rsrc = (const float4*)&g_rmn[b][0][0];
    for (int t = tid; t < DIM * 64 / 4; t += 128) ((float4*)s_rm)[t] = rsrc[t];
    __syncthreads();

    int l = blockIdx.x * 128 + tid;
    float qv[DIM];
    const float4* qp = (const float4*)&q[((size_t)b * LEN + l) * DIM];
#pragma unroll
    for (int t = 0; t < 16; t++) {
        float4 v = qp[t];
        qv[4 * t] = v.x; qv[4 * t + 1] = v.y; qv[4 * t + 2] = v.z; qv[4 * t + 3] = v.w;
    }
    float ss = 0.f;
#pragma unroll
    for (int d = 0; d < DIM; d++) ss += qv[d] * qv[d];
    float inv = rsqrtf(ss);
#pragma unroll
    for (int d = 0; d < DIM; d++) qv[d] *= inv;
    float4* qd = (float4*)&g_qn[b][l][0];
#pragma unroll
    for (int t = 0; t < 16; t++)
        qd[t] = make_float4(qv[4 * t], qv[4 * t + 1], qv[4 * t + 2], qv[4 * t + 3]);

    for (int r = 0; r < RN; r++) {
        float bp = -1e30f, bn = -1e30f;
        int bpi = 0, bni = 0;
        for (int k = 0; k < 16; k++) {
            float acc = 0.f;
#pragma unroll
            for (int d = 0; d < DIM; d++) acc += qv[d] * s_rm[d * 64 + r * 16 + k];
            if (acc > bp)  { bp = acc;  bpi = k; }
            if (-acc > bn) { bn = -acc; bni = k; }
        }
        g_hash[b][r][l] = (bn > bp) ? (16 + bni) : bpi;
    }
}

// ---------------- K2: stable counting sort per (b,r) ----------------
__global__ void __launch_bounds__(256) k_sort() {
    int b = blockIdx.x >> 2, r = blockIdx.x & 3;
    __shared__ int hist[32][257];
    __shared__ int base[32];
    int t = threadIdx.x;
#pragma unroll
    for (int v = 0; v < 32; v++) hist[v][t] = 0;
    __syncthreads();
    int h[8];
#pragma unroll
    for (int e = 0; e < 8; e++) {
        h[e] = g_hash[b][r][t * 8 + e];
        hist[h[e]][t]++;
    }
    __syncthreads();
    if (t < 32) {
        int run = 0;
        for (int i = 0; i < 256; i++) { int x = hist[t][i]; hist[t][i] = run; run += x; }
        base[t] = run;
    }
    __syncthreads();
    if (t == 0) {
        int run = 0;
        for (int v = 0; v < 32; v++) { int x = base[v]; base[v] = run; run += x; }
    }
    __syncthreads();
#pragma unroll
    for (int e = 0; e < 8; e++) {
        int l = t * 8 + e, v = h[e];
        int off = hist[v][t];
        hist[v][t] = off + 1;
        int pos = base[v] + off;
        g_hidx[b][r][pos] = l;
        g_oidx[b][r][l] = pos;
    }
}

// ---------------- K3: bf16-split mma.sync score GEMM (R13 verbatim) ----------------
#define SM3_TOTAL (4096 + 2 * NK * XSTR * 2)

__global__ void __launch_bounds__(1024) k_scores() {
    int n = blockIdx.x, r = blockIdx.y, b = blockIdx.z;
    extern __shared__ char sm3[];
    int2* kmeta = (int2*)sm3;
    __nv_bfloat16* xh = (__nv_bfloat16*)(sm3 + 4096);
    __nv_bfloat16* xl = (__nv_bfloat16*)(sm3 + 4096 + NK * XSTR * 2);
    int tid = threadIdx.x;
    int prevbase = ((n + NB2 - 1) & (NB2 - 1)) * CH;

    for (int j = tid; j < NK; j += 1024) {
        int keypos = (j < CH) ? (prevbase + j) : (n * CH + j - CH);
        int ki = g_hidx[b][r][keypos];
        int kh = g_hash[b][r][ki];
        int pc = 0;
#pragma unroll
        for (int rr = 0; rr < RN; rr++)
            pc |= ((g_oidx[b][rr][ki] >> 7) & 15) << (8 * rr);
        kmeta[j] = make_int2((kh << 16) | ki, pc);
    }
    __syncthreads();

    for (int t = tid; t < NK * 16; t += 1024) {
        int row = t >> 4, cg = t & 15;
        int ki = kmeta[row].x & 0xFFFF;
        float4 v = *(const float4*)&g_qn[b][ki][cg * 4];
        uint2 p0 = split2(make_float2(v.x, v.y));
        uint2 p1 = split2(make_float2(v.z, v.w));
        *(uint2*)&xh[row * XSTR + cg * 4] = make_uint2(p0.x, p1.x);
        *(uint2*)&xl[row * XSTR + cg * 4] = make_uint2(p0.y, p1.y);
    }
    __syncthreads();

    int wid = tid >> 5, lane = tid & 31;
    int wm = wid >> 2, wn = wid & 3;
    int i0 = wm * 16, j0 = wn * 64;
    int g = lane >> 2, t4 = lane & 3;

    float acc[8][4];
#pragma unroll
    for (int nt = 0; nt < 8; nt++)
#pragma unroll
        for (int c = 0; c < 4; c++) acc[nt][c] = 0.f;

    const __nv_bfloat16* Ah = xh + (CH + i0) * XSTR;
    const __nv_bfloat16* Al = xl + (CH + i0) * XSTR;
#pragma unroll
    for (int ks = 0; ks < 4; ks++) {
        int k0 = ks * 16 + 2 * t4;
        uint32_t ah[4], al[4];
        ah[0] = *(const uint32_t*)&Ah[g * XSTR + k0];
        ah[1] = *(const uint32_t*)&Ah[(g + 8) * XSTR + k0];
        ah[2] = *(const uint32_t*)&Ah[g * XSTR + k0 + 8];
        ah[3] = *(const uint32_t*)&Ah[(g + 8) * XSTR + k0 + 8];
        al[0] = *(const uint32_t*)&Al[g * XSTR + k0];
        al[1] = *(const uint32_t*)&Al[(g + 8) * XSTR + k0];
        al[2] = *(const uint32_t*)&Al[g * XSTR + k0 + 8];
        al[3] = *(const uint32_t*)&Al[(g + 8) * XSTR + k0 + 8];
#pragma unroll
        for (int nt = 0; nt < 8; nt++) {
            int rowb = (j0 + nt * 8 + g) * XSTR + k0;
            uint32_t bh0 = *(const uint32_t*)&xh[rowb];
            uint32_t bh1 = *(const uint32_t*)&xh[rowb + 8];
            uint32_t bl0 = *(const uint32_t*)&xl[rowb];
            uint32_t bl1 = *(const uint32_t*)&xl[rowb + 8];
            mma_bf16(acc[nt], ah, bh0, bh1);
            mma_bf16(acc[nt], ah, bl0, bl1);
            mma_bf16(acc[nt], al, bh0, bh1);
        }
    }

    int ia = i0 + g, ib = i0 + g + 8;
    int2 qa = kmeta[CH + ia], qb = kmeta[CH + ib];
    int qidxa = qa.x & 0xFFFF, qha = qa.x >> 16, npa = qa.y;
    int qidxb = qb.x & 0xFFFF, qhb = qb.x >> 16, npb = qb.y;
    int ppa = ((npa | 0x10101010) - 0x01010101) & 0x0f0f0f0f;
    int ppb = ((npb | 0x10101010) - 0x01010101) & 0x0f0f0f0f;
    float* rowa = &g_sc[b][r][n * CH + ia][0];
    float* rowb = &g_sc[b][r][n * CH + ib][0];
#pragma unroll
    for (int nt = 0; nt < 8; nt++) {
        int j = j0 + nt * 8 + 2 * t4;
        int4 km = *(const int4*)&kmeta[j];
        int kj0 = km.x & 0xFFFF, kh0 = km.x >> 16, kc0 = km.y;
        int kj1 = km.z & 0xFFFF, kh1 = km.z >> 16, kc1 = km.w;
        float o00 = acc[nt][0] * 0.125f, o01 = acc[nt][1] * 0.125f;
        float o10 = acc[nt][2] * 0.125f, o11 = acc[nt][3] * 0.125f;
        if (qidxa == kj0)                      o00 = -100000.0f;
        else if (qidxa < kj0 || qha != kh0)    o00 = -1000000000.0f;
        if (qidxa == kj1)                      o01 = -100000.0f;
        else if (qidxa < kj1 || qha != kh1)    o01 = -1000000000.0f;
        if (qidxb == kj0)                      o10 = -100000.0f;
        else if (qidxb < kj0 || qhb != kh0)    o10 = -1000000000.0f;
        if (qidxb == kj1)                      o11 = -100000.0f;
        else if (qidxb < kj1 || qhb != kh1)    o11 = -1000000000.0f;
        unsigned m;
        m = __vcmpeq4((unsigned)kc0, (unsigned)npa) | __vcmpeq4((unsigned)kc0, (unsigned)ppa);
        o00 -= c_log4[(__popc(m) >> 3) - 1];
        m = __vcmpeq4((unsigned)kc1, (unsigned)npa) | __vcmpeq4((unsigned)kc1, (unsigned)ppa);
        o01 -= c_log4[(__popc(m) >> 3) - 1];
        m = __vcmpeq4((unsigned)kc0, (unsigned)npb) | __vcmpeq4((unsigned)kc0, (unsigned)ppb);
        o10 -= c_log4[(__popc(m) >> 3) - 1];
        m = __vcmpeq4((unsigned)kc1, (unsigned)npb) | __vcmpeq4((unsigned)kc1, (unsigned)ppb);
        o11 -= c_log4[(__popc(m) >> 3) - 1];
        *(float2*)&rowa[j] = make_float2(o00, o01);
        *(float2*)&rowb[j] = make_float2(o10, o11);
    }
}

// ---------------- K4: joint softmax -> fp16 p in fragment-unit layout ----------------
__global__ void __launch_bounds__(512) k_softmax() {
    int b = blockIdx.y;
    int warp = threadIdx.x >> 5, lane = threadIdx.x & 31;
#pragma unroll 1
    for (int it = 0; it < 16; it++) {
        int l = blockIdx.x * 256 + it * 16 + warp;
        int srs[RN];
        float4 adj[RN][2];
        float mx = -3.4e38f;
#pragma unroll
        for (int r = 0; r < RN; r++) {
            srs[r] = g_oidx[b][r][l];
            const float4* srow = (const float4*)&g_sc[b][r][srs[r]][0];
            adj[r][0] = srow[lane];
            adj[r][1] = srow[lane + 32];
#pragma unroll
            for (int h = 0; h < 2; h++) {
                mx = fmaxf(mx, fmaxf(fmaxf(adj[r][h].x, adj[r][h].y),
                                     fmaxf(adj[r][h].z, adj[r][h].w)));
            }
        }
#pragma unroll
        for (int o = 16; o; o >>= 1) mx = fmaxf(mx, __shfl_xor_sync(0xffffffffu, mx, o));
        float sum = 0.f;
#pragma unroll
        for (int r = 0; r < RN; r++)
#pragma unroll
            for (int h = 0; h < 2; h++) {
                adj[r][h].x = fexp(adj[r][h].x - mx);
                adj[r][h].y = fexp(adj[r][h].y - mx);
                adj[r][h].z = fexp(adj[r][h].z - mx);
                adj[r][h].w = fexp(adj[r][h].w - mx);
                sum += adj[r][h].x + adj[r][h].y + adj[r][h].z + adj[r][h].w;
            }
#pragma unroll
        for (int o = 16; o; o >>= 1) sum += __shfl_xor_sync(0xffffffffu, sum, o);
        float inv = 1.0f / sum;
        // lane owns k-pairs P0 = 64h + 2*lane and P0+1. Unit u = (P>>3)*4 + (P&7)
        // holds pairs {P, P+4}; pairs P+4, P+5 come from lane+2 via shfl.
#pragma unroll
        for (int r = 0; r < RN; r++) {
            __half* prow = &g_ph[b][r][srs[r]][0];
#pragma unroll
            for (int h = 0; h < 2; h++) {
                float4 w = adj[r][h];
                uint32_t c0 = pack2h(w.x * inv, w.y * inv);
                uint32_t c1 = pack2h(w.z * inv, w.w * inv);
                uint32_t d0 = __shfl_down_sync(0xffffffffu, c0, 2);
                uint32_t d1 = __shfl_down_sync(0xffffffffu, c1, 2);
                if ((lane & 3) < 2) {
                    int P0 = 64 * h + 2 * lane;
                    int u0 = ((P0 >> 3) << 2) + (P0 & 7);
                    *(uint4*)&prow[u0 * 4] = make_uint4(c0, d0, c1, d1);
                }
            }
        }
    }
}

// ---------------- K5: f16 mma.sync p @ v_sorted, unit-layout fragments ----------------
#define SM5_TOTAL (2 * 64 * VSTR * 2)   // 2 planes x 64 rows x VSTR fp16 = 67584 B

__global__ void __launch_bounds__(512) k_av(const float* __restrict__ v) {
    int n = blockIdx.x, r = blockIdx.y, b = blockIdx.z;
    extern __shared__ char sm5[];
    __half* vh = (__half*)sm5;
    __half* vl = vh + 64 * VSTR;
    int tid = threadIdx.x;
    int prevbase = ((n + NB2 - 1) & (NB2 - 1)) * CH;

    // stage vT fp16 hi/lo in fragment-unit layout: unit u for pair P at
    // elem offset u*4 + word*2 (word = 0 if P&7<4 else 1, u from P-4 rule)
    for (int idx = tid; idx < 128 * 16; idx += 512) {
        int P = idx & 127, f = idx >> 7;
        int ja = 2 * P, jb = ja + 1;
        int kpa = (ja < CH) ? (prevbase + ja) : (n * CH + ja - CH);
        int kpb = (jb < CH) ? (prevbase + jb) : (n * CH + jb - CH);
        int kia = g_hidx[b][r][kpa];
        int kib = g_hidx[b][r][kpb];
        float4 va = *(const float4*)&v[((size_t)b * LEN + kia) * DIM + f * 4];
        float4 vb = *(const float4*)&v[((size_t)b * LEN + kib) * DIM + f * 4];
        float pa[4] = {va.x, va.y, va.z, va.w};
        float pb[4] = {vb.x, vb.y, vb.z, vb.w};
        int t8 = P & 7;
        int off = ((P >> 3) << 4) + ((t8 & 3) << 2) + ((t8 >> 2) << 1);
#pragma unroll
        for (int c = 0; c < 4; c++) {
            uint2 s = split2h(make_float2(pa[c], pb[c]));
            *(uint32_t*)&vh[(f * 4 + c) * VSTR + off] = s.x;
            *(uint32_t*)&vl[(f * 4 + c) * VSTR + off] = s.y;
        }
    }
    __syncthreads();

    int wid = tid >> 5, lane = tid & 31;
    int wm = wid >> 1, wn = wid & 1;
    int i0 = wm * 16, d0 = wn * 32;
    int g = lane >> 2, t4 = lane & 3;

    float acc[4][4];
#pragma unroll
    for (int nt = 0; nt < 4; nt++)
#pragma unroll
        for (int c = 0; c < 4; c++) acc[nt][c] = 0.f;

    const __half* p0 = &g_ph[b][r][n * CH + i0 + g][0];
    const __half* p8 = &g_ph[b][r][n * CH + i0 + g + 8][0];
#pragma unroll 4
    for (int ks = 0; ks < 16; ks++) {
        int uoff = (ks * 4 + t4) * 4;
        uint2 ua = *(const uint2*)&p0[uoff];   // {pair k0, pair k0+8} row g
        uint2 ub = *(const uint2*)&p8[uoff];   // row g+8
        uint32_t a[4] = {ua.x, ub.x, ua.y, ub.y};
#pragma unroll
        for (int nt = 0; nt < 4; nt++) {
            int rowb = (d0 + nt * 8 + g) * VSTR + uoff;
            uint2 bh = *(const uint2*)&vh[rowb];
            uint2 bl = *(const uint2*)&vl[rowb];
            mma_f16(acc[nt], a, bh.x, bh.y);
            mma_f16(acc[nt], a, bl.x, bl.y);
        }
    }

    int ia = i0 + g, ib = ia + 8;
#pragma unroll
    for (int nt = 0; nt < 4; nt++) {
        int d = d0 + nt * 8 + 2 * t4;
        *(float2*)&g_attn[b][r][n * CH + ia][d] = make_float2(acc[nt][0], acc[nt][1]);
        *(float2*)&g_attn[b][r][n * CH + ib][d] = make_float2(acc[nt][2], acc[nt][3]);
    }
}

// ---------------- K6: gather rounds back to original order, sum ----------------
__global__ void __launch_bounds__(256) k_out(float* __restrict__ out) {
    int gid = blockIdx.x * 256 + threadIdx.x;
    int dq = gid & 15;
    int l = (gid >> 4) & (LEN - 1);
    int b = gid >> 15;
    float4 s = make_float4(0.f, 0.f, 0.f, 0.f);
#pragma unroll
    for (int r = 0; r < RN; r++) {
        int sIdx = g_oidx[b][r][l];
        float4 a = *(const float4*)&g_attn[b][r][sIdx][dq * 4];
        s.x += a.x; s.y += a.y; s.z += a.z; s.w += a.w;
    }
    *(float4*)&out[((size_t)b * LEN + l) * DIM + dq * 4] = s;
}

// ---------------- launch ----------------
extern "C" void kernel_launch(void* const* d_in, const int* in_sizes, int n_in,
                              void* d_out, int out_size) {
    const float* q  = (const float*)d_in[0];
    const float* v  = (const float*)d_in[1];
    const float* rm = (const float*)d_in[2];
    float* out = (float*)d_out;

    cudaFuncSetAttribute(k_scores, cudaFuncAttributeMaxDynamicSharedMemorySize, SM3_TOTAL);
    cudaFuncSetAttribute(k_av,     cudaFuncAttributeMaxDynamicSharedMemorySize, SM5_TOTAL);

    k_rmn<<<BHN, 64>>>(rm);
    k_hash<<<dim3(LEN / 128, BHN), 128>>>(q);
    k_sort<<<BHN * RN, 256>>>();
    k_scores<<<dim3(NB2, RN, BHN), 1024, SM3_TOTAL>>>();   // launch #3 -> ncu slot
    k_softmax<<<dim3(LEN / 256, BHN), 512>>>();
    k_av<<<dim3(NB2, RN, BHN), 512, SM5_TOTAL>>>(v);
    k_out<<<(BHN * LEN * 16) / 256, 256>>>(out);
}

// round 16
// speedup vs baseline: 1.0996x; 1.0184x over previous
#include <cuda_runtime.h>
#include <cuda_bf16.h>
#include <cuda_fp16.h>
#include <stdint.h>

#define BHN 16
#define LEN 2048
#define DIM 64
#define RN  4
#define NB2 16
#define CH  128
#define NK  256
#define XSTR 72    // k_scores staged row stride (fp16 elements)
#define VSTR 264   // k_av vT row stride (fp16 elements)

typedef unsigned long long ull;

// ---------------- scratch (device globals; allocation-free) ----------------
__device__ float    g_qn  [BHN][LEN][DIM];
__device__ float    g_rmn [BHN][DIM][64];
__device__ int      g_hash[BHN][RN][LEN];
__device__ int      g_hidx[BHN][RN][LEN];
__device__ int      g_oidx[BHN][RN][LEN];
__device__ float    g_sc  [BHN][RN][LEN][NK];   // adjusted scores (read-only after K3)
// p as fp16 in fragment-unit layout: unit u = (P>>3)*4 + (P&7) holds pairs {P, P+4}
__device__ __align__(16) __half g_ph[BHN][RN][LEN][NK];
__device__ float    g_attn[BHN][RN][LEN][DIM];

__constant__ float c_log4[4] = {0.0f, 0.6931471805599453f, 1.0986122886681098f, 1.3862943611198906f};

// fast exp on the FMA pipe — R2's exact version
__device__ __forceinline__ float fexp(float x) {
    x = fmaxf(x, -87.0f);
    float t = fmaf(x, 1.4426950408889634f, 12582912.0f);
    int n = __float_as_int(t) - 0x4B400000;
    float fi = t - 12582912.0f;
    float z = fmaf(fi, -0.6931471805599453f, x);
    float p = 8.3333337e-3f;
    p = fmaf(p, z, 4.1666668e-2f);
    p = fmaf(p, z, 0.16666667f);
    p = fmaf(p, z, 0.5f);
    p = fmaf(p, z, 1.0f);
    p = fmaf(p, z, 1.0f);
    return p * __int_as_float((n + 127) << 23);
}

// ---------------- mma.sync m16n8k16 f16 ----------------
__device__ __forceinline__ void mma_f16(float* c, const uint32_t* a, uint32_t b0, uint32_t b1) {
    asm volatile(
        "mma.sync.aligned.m16n8k16.row.col.f32.f16.f16.f32 "
        "{%0,%1,%2,%3}, {%4,%5,%6,%7}, {%8,%9}, {%0,%1,%2,%3};"
        : "+f"(c[0]), "+f"(c[1]), "+f"(c[2]), "+f"(c[3])
        : "r"(a[0]), "r"(a[1]), "r"(a[2]), "r"(a[3]), "r"(b0), "r"(b1));
}

// split float2 -> packed fp16 hi (x) and lo (y); low half = .x
__device__ __forceinline__ uint2 split2h(float2 f) {
    __half h0 = __float2half_rn(f.x);
    __half h1 = __float2half_rn(f.y);
    __half l0 = __float2half_rn(f.x - __half2float(h0));
    __half l1 = __float2half_rn(f.y - __half2float(h1));
    uint2 r;
    r.x = ((uint32_t)__half_as_ushort(h1) << 16) | __half_as_ushort(h0);
    r.y = ((uint32_t)__half_as_ushort(l1) << 16) | __half_as_ushort(l0);
    return r;
}
__device__ __forceinline__ uint32_t pack2h(float a, float b) {
    __half2 h = __floats2half2_rn(a, b);   // .x = a (low)
    return *(uint32_t*)&h;
}

// ---------------- K0: normalize rand_matrix columns ----------------
__global__ void k_rmn(const float* __restrict__ rm) {
    int b = blockIdx.x;
    int j = threadIdx.x;
    float s = 0.f;
    for (int d = 0; d < DIM; d++) {
        float v = rm[(size_t)(b * DIM + d) * 64 + j];
        s += v * v;
    }
    float inv = rsqrtf(s);
    for (int d = 0; d < DIM; d++)
        g_rmn[b][d][j] = rm[(size_t)(b * DIM + d) * 64 + j] * inv;
}

// ---------------- K1: normalize q + hashes ----------------
__global__ void __launch_bounds__(128) k_hash(const float* __restrict__ q) {
    int b = blockIdx.y;
    __shared__ float s_rm[DIM * 64];
    int tid = threadIdx.x;
    const float4* rsrc = (const float4*)&g_rmn[b][0][0];
    for (int t = tid; t < DIM * 64 / 4; t += 128) ((float4*)s_rm)[t] = rsrc[t];
    __syncthreads();

    int l = blockIdx.x * 128 + tid;
    float qv[DIM];
    const float4* qp = (const float4*)&q[((size_t)b * LEN + l) * DIM];
#pragma unroll
    for (int t = 0; t < 16; t++) {
        float4 v = qp[t];
        qv[4 * t] = v.x; qv[4 * t + 1] = v.y; qv[4 * t + 2] = v.z; qv[4 * t + 3] = v.w;
    }
    float ss = 0.f;
#pragma unroll
    for (int d = 0; d < DIM; d++) ss += qv[d] * qv[d];
    float inv = rsqrtf(ss);
#pragma unroll
    for (int d = 0; d < DIM; d++) qv[d] *= inv;
    float4* qd = (float4*)&g_qn[b][l][0];
#pragma unroll
    for (int t = 0; t < 16; t++)
        qd[t] = make_float4(qv[4 * t], qv[4 * t + 1], qv[4 * t + 2], qv[4 * t + 3]);

    for (int r = 0; r < RN; r++) {
        float bp = -1e30f, bn = -1e30f;
        int bpi = 0, bni = 0;
        for (int k = 0; k < 16; k++) {
            float acc = 0.f;
#pragma unroll
            for (int d = 0; d < DIM; d++) acc += qv[d] * s_rm[d * 64 + r * 16 + k];
            if (acc > bp)  { bp = acc;  bpi = k; }
            if (-acc > bn) { bn = -acc; bni = k; }
        }
        g_hash[b][r][l] = (bn > bp) ? (16 + bni) : bpi;
    }
}

// ---------------- K2: stable counting sort per (b,r) ----------------
__global__ void __launch_bounds__(256) k_sort() {
    int b = blockIdx.x >> 2, r = blockIdx.x & 3;
    __shared__ int hist[32][257];
    __shared__ int base[32];
    int t = threadIdx.x;
#pragma unroll
    for (int v = 0; v < 32; v++) hist[v][t] = 0;
    __syncthreads();
    int h[8];
#pragma unroll
    for (int e = 0; e < 8; e++) {
        h[e] = g_hash[b][r][t * 8 + e];
        hist[h[e]][t]++;
    }
    __syncthreads();
    if (t < 32) {
        int run = 0;
        for (int i = 0; i < 256; i++) { int x = hist[t][i]; hist[t][i] = run; run += x; }
        base[t] = run;
    }
    __syncthreads();
    if (t == 0) {
        int run = 0;
        for (int v = 0; v < 32; v++) { int x = base[v]; base[v] = run; run += x; }
    }
    __syncthreads();
#pragma unroll
    for (int e = 0; e < 8; e++) {
        int l = t * 8 + e, v = h[e];
        int off = hist[v][t];
        hist[v][t] = off + 1;
        int pos = base[v] + off;
        g_hidx[b][r][pos] = l;
        g_oidx[b][r][l] = pos;
    }
}

// ---------------- K3: fp16 2-term mma.sync score GEMM ----------------
// A = fp16(q) (hi plane only); B = k split fp16 hi/lo. s = Ah*Bh + Ah*Bl.
#define SM3_TOTAL (4096 + 2 * NK * XSTR * 2)

__global__ void __launch_bounds__(1024) k_scores() {
    int n = blockIdx.x, r = blockIdx.y, b = blockIdx.z;
    extern __shared__ char sm3[];
    int2* kmeta = (int2*)sm3;
    __half* xh = (__half*)(sm3 + 4096);
    __half* xl = xh + NK * XSTR;
    int tid = threadIdx.x;
    int prevbase = ((n + NB2 - 1) & (NB2 - 1)) * CH;

    for (int j = tid; j < NK; j += 1024) {
        int keypos = (j < CH) ? (prevbase + j) : (n * CH + j - CH);
        int ki = g_hidx[b][r][keypos];
        int kh = g_hash[b][r][ki];
        int pc = 0;
#pragma unroll
        for (int rr = 0; rr < RN; rr++)
            pc |= ((g_oidx[b][rr][ki] >> 7) & 15) << (8 * rr);
        kmeta[j] = make_int2((kh << 16) | ki, pc);
    }
    __syncthreads();

    for (int t = tid; t < NK * 16; t += 1024) {
        int row = t >> 4, cg = t & 15;
        int ki = kmeta[row].x & 0xFFFF;
        float4 v = *(const float4*)&g_qn[b][ki][cg * 4];
        uint2 p0 = split2h(make_float2(v.x, v.y));
        uint2 p1 = split2h(make_float2(v.z, v.w));
        *(uint2*)&xh[row * XSTR + cg * 4] = make_uint2(p0.x, p1.x);
        *(uint2*)&xl[row * XSTR + cg * 4] = make_uint2(p0.y, p1.y);
    }
    __syncthreads();

    int wid = tid >> 5, lane = tid & 31;
    int wm = wid >> 2, wn = wid & 3;
    int i0 = wm * 16, j0 = wn * 64;
    int g = lane >> 2, t4 = lane & 3;

    float acc[8][4];
#pragma unroll
    for (int nt = 0; nt < 8; nt++)
#pragma unroll
        for (int c = 0; c < 4; c++) acc[nt][c] = 0.f;

    const __half* Ah = xh + (CH + i0) * XSTR;
#pragma unroll
    for (int ks = 0; ks < 4; ks++) {
        int k0 = ks * 16 + 2 * t4;
        uint32_t ah[4];
        ah[0] = *(const uint32_t*)&Ah[g * XSTR + k0];
        ah[1] = *(const uint32_t*)&Ah[(g + 8) * XSTR + k0];
        ah[2] = *(const uint32_t*)&Ah[g * XSTR + k0 + 8];
        ah[3] = *(const uint32_t*)&Ah[(g + 8) * XSTR + k0 + 8];
#pragma unroll
        for (int nt = 0; nt < 8; nt++) {
            int rowb = (j0 + nt * 8 + g) * XSTR + k0;
            uint32_t bh0 = *(const uint32_t*)&xh[rowb];
            uint32_t bh1 = *(const uint32_t*)&xh[rowb + 8];
            uint32_t bl0 = *(const uint32_t*)&xl[rowb];
            uint32_t bl1 = *(const uint32_t*)&xl[rowb + 8];
            mma_f16(acc[nt], ah, bh0, bh1);
            mma_f16(acc[nt], ah, bl0, bl1);
        }
    }

    int ia = i0 + g, ib = i0 + g + 8;
    int2 qa = kmeta[CH + ia], qb = kmeta[CH + ib];
    int qidxa = qa.x & 0xFFFF, qha = qa.x >> 16, npa = qa.y;
    int qidxb = qb.x & 0xFFFF, qhb = qb.x >> 16, npb = qb.y;
    int ppa = ((npa | 0x10101010) - 0x01010101) & 0x0f0f0f0f;
    int ppb = ((npb | 0x10101010) - 0x01010101) & 0x0f0f0f0f;
    float* rowa = &g_sc[b][r][n * CH + ia][0];
    float* rowb = &g_sc[b][r][n * CH + ib][0];
#pragma unroll
    for (int nt = 0; nt < 8; nt++) {
        int j = j0 + nt * 8 + 2 * t4;
        int4 km = *(const int4*)&kmeta[j];
        int kj0 = km.x & 0xFFFF, kh0 = km.x >> 16, kc0 = km.y;
        int kj1 = km.z & 0xFFFF, kh1 = km.z >> 16, kc1 = km.w;
        float o00 = acc[nt][0] * 0.125f, o01 = acc[nt][1] * 0.125f;
        float o10 = acc[nt][2] * 0.125f, o11 = acc[nt][3] * 0.125f;
        if (qidxa == kj0)                      o00 = -100000.0f;
        else if (qidxa < kj0 || qha != kh0)    o00 = -1000000000.0f;
        if (qidxa == kj1)                      o01 = -100000.0f;
        else if (qidxa < kj1 || qha != kh1)    o01 = -1000000000.0f;
        if (qidxb == kj0)                      o10 = -100000.0f;
        else if (qidxb < kj0 || qhb != kh0)    o10 = -1000000000.0f;
        if (qidxb == kj1)                      o11 = -100000.0f;
        else if (qidxb < kj1 || qhb != kh1)    o11 = -1000000000.0f;
        unsigned m;
        m = __vcmpeq4((unsigned)kc0, (unsigned)npa) | __vcmpeq4((unsigned)kc0, (unsigned)ppa);
        o00 -= c_log4[(__popc(m) >> 3) - 1];
        m = __vcmpeq4((unsigned)kc1, (unsigned)npa) | __vcmpeq4((unsigned)kc1, (unsigned)ppa);
        o01 -= c_log4[(__popc(m) >> 3) - 1];
        m = __vcmpeq4((unsigned)kc0, (unsigned)npb) | __vcmpeq4((unsigned)kc0, (unsigned)ppb);
        o10 -= c_log4[(__popc(m) >> 3) - 1];
        m = __vcmpeq4((unsigned)kc1, (unsigned)npb) | __vcmpeq4((unsigned)kc1, (unsigned)ppb);
        o11 -= c_log4[(__popc(m) >> 3) - 1];
        *(float2*)&rowa[j] = make_float2(o00, o01);
        *(float2*)&rowb[j] = make_float2(o10, o11);
    }
}

// ---------------- K4: joint softmax -> fp16 p in fragment-unit layout ----------------
__global__ void __launch_bounds__(512) k_softmax() {
    int b = blockIdx.y;
    int warp = threadIdx.x >> 5, lane = threadIdx.x & 31;
#pragma unroll 1
    for (int it = 0; it < 16; it++) {
        int l = blockIdx.x * 256 + it * 16 + warp;
        int srs[RN];
        float4 adj[RN][2];
        float mx = -3.4e38f;
#pragma unroll
        for (int r = 0; r < RN; r++) {
            srs[r] = g_oidx[b][r][l];
            const float4* srow = (const float4*)&g_sc[b][r][srs[r]][0];
            adj[r][0] = srow[lane];
            adj[r][1] = srow[lane + 32];
#pragma unroll
            for (int h = 0; h < 2; h++) {
                mx = fmaxf(mx, fmaxf(fmaxf(adj[r][h].x, adj[r][h].y),
                                     fmaxf(adj[r][h].z, adj[r][h].w)));
            }
        }
#pragma unroll
        for (int o = 16; o; o >>= 1) mx = fmaxf(mx, __shfl_xor_sync(0xffffffffu, mx, o));
        float sum = 0.f;
#pragma unroll
        for (int r = 0; r < RN; r++)
#pragma unroll
            for (int h = 0; h < 2; h++) {
                adj[r][h].x = fexp(adj[r][h].x - mx);
                adj[r][h].y = fexp(adj[r][h].y - mx);
                adj[r][h].z = fexp(adj[r][h].z - mx);
                adj[r][h].w = fexp(adj[r][h].w - mx);
                sum += adj[r][h].x + adj[r][h].y + adj[r][h].z + adj[r][h].w;
            }
#pragma unroll
        for (int o = 16; o; o >>= 1) sum += __shfl_xor_sync(0xffffffffu, sum, o);
        float inv = 1.0f / sum;
#pragma unroll
        for (int r = 0; r < RN; r++) {
            __half* prow = &g_ph[b][r][srs[r]][0];
#pragma unroll
            for (int h = 0; h < 2; h++) {
                float4 w = adj[r][h];
                uint32_t c0 = pack2h(w.x * inv, w.y * inv);
                uint32_t c1 = pack2h(w.z * inv, w.w * inv);
                uint32_t d0 = __shfl_down_sync(0xffffffffu, c0, 2);
                uint32_t d1 = __shfl_down_sync(0xffffffffu, c1, 2);
                if ((lane & 3) < 2) {
                    int P0 = 64 * h + 2 * lane;
                    int u0 = ((P0 >> 3) << 2) + (P0 & 7);
                    *(uint4*)&prow[u0 * 4] = make_uint4(c0, d0, c1, d1);
                }
            }
        }
    }
}

// ---------------- K5: f16 mma.sync p @ v_sorted, unit-layout fragments (R15 verbatim) ----------------
#define SM5_TOTAL (2 * 64 * VSTR * 2)

__global__ void __launch_bounds__(512) k_av(const float* __restrict__ v) {
    int n = blockIdx.x, r = blockIdx.y, b = blockIdx.z;
    extern __shared__ char sm5[];
    __half* vh = (__half*)sm5;
    __half* vl = vh + 64 * VSTR;
    int tid = threadIdx.x;
    int prevbase = ((n + NB2 - 1) & (NB2 - 1)) * CH;

    for (int idx = tid; idx < 128 * 16; idx += 512) {
        int P = idx & 127, f = idx >> 7;
        int ja = 2 * P, jb = ja + 1;
        int kpa = (ja < CH) ? (prevbase + ja) : (n * CH + ja - CH);
        int kpb = (jb < CH) ? (prevbase + jb) : (n * CH + jb - CH);
        int kia = g_hidx[b][r][kpa];
        int kib = g_hidx[b][r][kpb];
        float4 va = *(const float4*)&v[((size_t)b * LEN + kia) * DIM + f * 4];
        float4 vb = *(const float4*)&v[((size_t)b * LEN + kib) * DIM + f * 4];
        float pa[4] = {va.x, va.y, va.z, va.w};
        float pb[4] = {vb.x, vb.y, vb.z, vb.w};
        int t8 = P & 7;
        int off = ((P >> 3) << 4) + ((t8 & 3) << 2) + ((t8 >> 2) << 1);
#pragma unroll
        for (int c = 0; c < 4; c++) {
            uint2 s = split2h(make_float2(pa[c], pb[c]));
            *(uint32_t*)&vh[(f * 4 + c) * VSTR + off] = s.x;
            *(uint32_t*)&vl[(f * 4 + c) * VSTR + off] = s.y;
        }
    }
    __syncthreads();

    int wid = tid >> 5, lane = tid & 31;
    int wm = wid >> 1, wn = wid & 1;
    int i0 = wm * 16, d0 = wn * 32;
    int g = lane >> 2, t4 = lane & 3;

    float acc[4][4];
#pragma unroll
    for (int nt = 0; nt < 4; nt++)
#pragma unroll
        for (int c = 0; c < 4; c++) acc[nt][c] = 0.f;

    const __half* p0 = &g_ph[b][r][n * CH + i0 + g][0];
    const __half* p8 = &g_ph[b][r][n * CH + i0 + g + 8][0];
#pragma unroll 4
    for (int ks = 0; ks < 16; ks++) {
        int uoff = (ks * 4 + t4) * 4;
        uint2 ua = *(const uint2*)&p0[uoff];
        uint2 ub = *(const uint2*)&p8[uoff];
        uint32_t a[4] = {ua.x, ub.x, ua.y, ub.y};
#pragma unroll
        for (int nt = 0; nt < 4; nt++) {
            int rowb = (d0 + nt * 8 + g) * VSTR + uoff;
            uint2 bh = *(const uint2*)&vh[rowb];
            uint2 bl = *(const uint2*)&vl[rowb];
            mma_f16(acc[nt], a, bh.x, bh.y);
            mma_f16(acc[nt], a, bl.x, bl.y);
        }
    }

    int ia = i0 + g, ib = ia + 8;
#pragma unroll
    for (int nt = 0; nt < 4; nt++) {
        int d = d0 + nt * 8 + 2 * t4;
        *(float2*)&g_attn[b][r][n * CH + ia][d] = make_float2(acc[nt][0], acc[nt][1]);
        *(float2*)&g_attn[b][r][n * CH + ib][d] = make_float2(acc[nt][2], acc[nt][3]);
    }
}

// ---------------- K6: gather rounds back to original order, sum ----------------
__global__ void __launch_bounds__(256) k_out(float* __restrict__ out) {
    int gid = blockIdx.x * 256 + threadIdx.x;
    int dq = gid & 15;
    int l = (gid >> 4) & (LEN - 1);
    int b = gid >> 15;
    float4 s = make_float4(0.f, 0.f, 0.f, 0.f);
#pragma unroll
    for (int r = 0; r < RN; r++) {
        int sIdx = g_oidx[b][r][l];
        float4 a = *(const float4*)&g_attn[b][r][sIdx][dq * 4];
        s.x += a.x; s.y += a.y; s.z += a.z; s.w += a.w;
    }
    *(float4*)&out[((size_t)b * LEN + l) * DIM + dq * 4] = s;
}

// ---------------- launch ----------------
extern "C" void kernel_launch(void* const* d_in, const int* in_sizes, int n_in,
                              void* d_out, int out_size) {
    const float* q  = (const float*)d_in[0];
    const float* v  = (const float*)d_in[1];
    const float* rm = (const float*)d_in[2];
    float* out = (float*)d_out;

    cudaFuncSetAttribute(k_scores, cudaFuncAttributeMaxDynamicSharedMemorySize, SM3_TOTAL);
    cudaFuncSetAttribute(k_av,     cudaFuncAttributeMaxDynamicSharedMemorySize, SM5_TOTAL);

    k_rmn<<<BHN, 64>>>(rm);
    k_hash<<<dim3(LEN / 128, BHN), 128>>>(q);
    k_sort<<<BHN * RN, 256>>>();
    k_scores<<<dim3(NB2, RN, BHN), 1024, SM3_TOTAL>>>();   // launch #3 -> ncu slot
    k_softmax<<<dim3(LEN / 256, BHN), 512>>>();
    k_av<<<dim3(NB2, RN, BHN), 512, SM5_TOTAL>>>(v);
    k_out<<<(BHN * LEN * 16) / 256, 256>>>(out);
}

// round 17
// speedup vs baseline: 1.1332x; 1.0306x over previous
#include <cuda_runtime.h>
#include <cuda_bf16.h>
#include <cuda_fp16.h>
#include <stdint.h>

#define BHN 16
#define LEN 2048
#define DIM 64
#define RN  4
#define NB2 16
#define CH  128
#define NK  256
#define XSTR 72    // k_scores staged row stride (fp16 elements)
#define VSTR 264   // k_av vT row stride (fp16 elements)

typedef unsigned long long ull;

// ---------------- scratch (device globals; allocation-free) ----------------
__device__ float    g_qn  [BHN][LEN][DIM];
__device__ float    g_rmn [BHN][DIM][64];
__device__ int      g_hash[BHN][RN][LEN];
__device__ int      g_hidx[BHN][RN][LEN];
__device__ int      g_oidx[BHN][RN][LEN];
// adjusted scores in fp16 (64 MB). masks: self = -30000, dead = -60000.
__device__ __align__(16) __half g_sh[BHN][RN][LEN][NK];
// p as fp16 in fragment-unit layout: unit u = (P>>3)*4 + (P&7) holds pairs {P, P+4}
__device__ __align__(16) __half g_ph[BHN][RN][LEN][NK];
__device__ float    g_attn[BHN][RN][LEN][DIM];

__constant__ float c_log4[4] = {0.0f, 0.6931471805599453f, 1.0986122886681098f, 1.3862943611198906f};

// fast exp on the FMA pipe — R2's exact version
__device__ __forceinline__ float fexp(float x) {
    x = fmaxf(x, -87.0f);
    float t = fmaf(x, 1.4426950408889634f, 12582912.0f);
    int n = __float_as_int(t) - 0x4B400000;
    float fi = t - 12582912.0f;
    float z = fmaf(fi, -0.6931471805599453f, x);
    float p = 8.3333337e-3f;
    p = fmaf(p, z, 4.1666668e-2f);
    p = fmaf(p, z, 0.16666667f);
    p = fmaf(p, z, 0.5f);
    p = fmaf(p, z, 1.0f);
    p = fmaf(p, z, 1.0f);
    return p * __int_as_float((n + 127) << 23);
}

// ---------------- mma.sync m16n8k16 f16 ----------------
__device__ __forceinline__ void mma_f16(float* c, const uint32_t* a, uint32_t b0, uint32_t b1) {
    asm volatile(
        "mma.sync.aligned.m16n8k16.row.col.f32.f16.f16.f32 "
        "{%0,%1,%2,%3}, {%4,%5,%6,%7}, {%8,%9}, {%0,%1,%2,%3};"
        : "+f"(c[0]), "+f"(c[1]), "+f"(c[2]), "+f"(c[3])
        : "r"(a[0]), "r"(a[1]), "r"(a[2]), "r"(a[3]), "r"(b0), "r"(b1));
}

// split float2 -> packed fp16 hi (x) and lo (y); low half = .x
__device__ __forceinline__ uint2 split2h(float2 f) {
    __half h0 = __float2half_rn(f.x);
    __half h1 = __float2half_rn(f.y);
    __half l0 = __float2half_rn(f.x - __half2float(h0));
    __half l1 = __float2half_rn(f.y - __half2float(h1));
    uint2 r;
    r.x = ((uint32_t)__half_as_ushort(h1) << 16) | __half_as_ushort(h0);
    r.y = ((uint32_t)__half_as_ushort(l1) << 16) | __half_as_ushort(l0);
    return r;
}
__device__ __forceinline__ uint32_t pack2h(float a, float b) {
    __half2 h = __floats2half2_rn(a, b);   // .x = a (low)
    return *(uint32_t*)&h;
}
__device__ __forceinline__ float2 unpk2h(uint32_t u) {
    __half2 h = *(__half2*)&u;
    return __half22float2(h);
}

// ---------------- K0: normalize rand_matrix columns ----------------
__global__ void k_rmn(const float* __restrict__ rm) {
    int b = blockIdx.x;
    int j = threadIdx.x;
    float s = 0.f;
    for (int d = 0; d < DIM; d++) {
        float v = rm[(size_t)(b * DIM + d) * 64 + j];
        s += v * v;
    }
    float inv = rsqrtf(s);
    for (int d = 0; d < DIM; d++)
        g_rmn[b][d][j] = rm[(size_t)(b * DIM + d) * 64 + j] * inv;
}

// ---------------- K1: normalize q + hashes ----------------
__global__ void __launch_bounds__(128) k_hash(const float* __restrict__ q) {
    int b = blockIdx.y;
    __shared__ float s_rm[DIM * 64];
    int tid = threadIdx.x;
    const float4* rsrc = (const float4*)&g_rmn[b][0][0];
    for (int t = tid; t < DIM * 64 / 4; t += 128) ((float4*)s_rm)[t] = rsrc[t];
    __syncthreads();

    int l = blockIdx.x * 128 + tid;
    float qv[DIM];
    const float4* qp = (const float4*)&q[((size_t)b * LEN + l) * DIM];
#pragma unroll
    for (int t = 0; t < 16; t++) {
        float4 v = qp[t];
        qv[4 * t] = v.x; qv[4 * t + 1] = v.y; qv[4 * t + 2] = v.z; qv[4 * t + 3] = v.w;
    }
    float ss = 0.f;
#pragma unroll
    for (int d = 0; d < DIM; d++) ss += qv[d] * qv[d];
    float inv = rsqrtf(ss);
#pragma unroll
    for (int d = 0; d < DIM; d++) qv[d] *= inv;
    float4* qd = (float4*)&g_qn[b][l][0];
#pragma unroll
    for (int t = 0; t < 16; t++)
        qd[t] = make_float4(qv[4 * t], qv[4 * t + 1], qv[4 * t + 2], qv[4 * t + 3]);

    for (int r = 0; r < RN; r++) {
        float bp = -1e30f, bn = -1e30f;
        int bpi = 0, bni = 0;
        for (int k = 0; k < 16; k++) {
            float acc = 0.f;
#pragma unroll
            for (int d = 0; d < DIM; d++) acc += qv[d] * s_rm[d * 64 + r * 16 + k];
            if (acc > bp)  { bp = acc;  bpi = k; }
            if (-acc > bn) { bn = -acc; bni = k; }
        }
        g_hash[b][r][l] = (bn > bp) ? (16 + bni) : bpi;
    }
}

// ---------------- K2: stable counting sort per (b,r) ----------------
__global__ void __launch_bounds__(256) k_sort() {
    int b = blockIdx.x >> 2, r = blockIdx.x & 3;
    __shared__ int hist[32][257];
    __shared__ int base[32];
    int t = threadIdx.x;
#pragma unroll
    for (int v = 0; v < 32; v++) hist[v][t] = 0;
    __syncthreads();
    int h[8];
#pragma unroll
    for (int e = 0; e < 8; e++) {
        h[e] = g_hash[b][r][t * 8 + e];
        hist[h[e]][t]++;
    }
    __syncthreads();
    if (t < 32) {
        int run = 0;
        for (int i = 0; i < 256; i++) { int x = hist[t][i]; hist[t][i] = run; run += x; }
        base[t] = run;
    }
    __syncthreads();
    if (t == 0) {
        int run = 0;
        for (int v = 0; v < 32; v++) { int x = base[v]; base[v] = run; run += x; }
    }
    __syncthreads();
#pragma unroll
    for (int e = 0; e < 8; e++) {
        int l = t * 8 + e, v = h[e];
        int off = hist[v][t];
        hist[v][t] = off + 1;
        int pos = base[v] + off;
        g_hidx[b][r][pos] = l;
        g_oidx[b][r][l] = pos;
    }
}

// ---------------- K3: fp16 2-term mma.sync score GEMM -> fp16 scores ----------------
#define SM3_TOTAL (4096 + 2 * NK * XSTR * 2)

__global__ void __launch_bounds__(1024) k_scores() {
    int n = blockIdx.x, r = blockIdx.y, b = blockIdx.z;
    extern __shared__ char sm3[];
    int2* kmeta = (int2*)sm3;
    __half* xh = (__half*)(sm3 + 4096);
    __half* xl = xh + NK * XSTR;
    int tid = threadIdx.x;
    int prevbase = ((n + NB2 - 1) & (NB2 - 1)) * CH;

    for (int j = tid; j < NK; j += 1024) {
        int keypos = (j < CH) ? (prevbase + j) : (n * CH + j - CH);
        int ki = g_hidx[b][r][keypos];
        int kh = g_hash[b][r][ki];
        int pc = 0;
#pragma unroll
        for (int rr = 0; rr < RN; rr++)
            pc |= ((g_oidx[b][rr][ki] >> 7) & 15) << (8 * rr);
        kmeta[j] = make_int2((kh << 16) | ki, pc);
    }
    __syncthreads();

    for (int t = tid; t < NK * 16; t += 1024) {
        int row = t >> 4, cg = t & 15;
        int ki = kmeta[row].x & 0xFFFF;
        float4 v = *(const float4*)&g_qn[b][ki][cg * 4];
        uint2 p0 = split2h(make_float2(v.x, v.y));
        uint2 p1 = split2h(make_float2(v.z, v.w));
        *(uint2*)&xh[row * XSTR + cg * 4] = make_uint2(p0.x, p1.x);
        *(uint2*)&xl[row * XSTR + cg * 4] = make_uint2(p0.y, p1.y);
    }
    __syncthreads();

    int wid = tid >> 5, lane = tid & 31;
    int wm = wid >> 2, wn = wid & 3;
    int i0 = wm * 16, j0 = wn * 64;
    int g = lane >> 2, t4 = lane & 3;

    float acc[8][4];
#pragma unroll
    for (int nt = 0; nt < 8; nt++)
#pragma unroll
        for (int c = 0; c < 4; c++) acc[nt][c] = 0.f;

    const __half* Ah = xh + (CH + i0) * XSTR;
#pragma unroll
    for (int ks = 0; ks < 4; ks++) {
        int k0 = ks * 16 + 2 * t4;
        uint32_t ah[4];
        ah[0] = *(const uint32_t*)&Ah[g * XSTR + k0];
        ah[1] = *(const uint32_t*)&Ah[(g + 8) * XSTR + k0];
        ah[2] = *(const uint32_t*)&Ah[g * XSTR + k0 + 8];
        ah[3] = *(const uint32_t*)&Ah[(g + 8) * XSTR + k0 + 8];
#pragma unroll
        for (int nt = 0; nt < 8; nt++) {
            int rowb = (j0 + nt * 8 + g) * XSTR + k0;
            uint32_t bh0 = *(const uint32_t*)&xh[rowb];
            uint32_t bh1 = *(const uint32_t*)&xh[rowb + 8];
            uint32_t bl0 = *(const uint32_t*)&xl[rowb];
            uint32_t bl1 = *(const uint32_t*)&xl[rowb + 8];
            mma_f16(acc[nt], ah, bh0, bh1);
            mma_f16(acc[nt], ah, bl0, bl1);
        }
    }

    int ia = i0 + g, ib = i0 + g + 8;
    int2 qa = kmeta[CH + ia], qb = kmeta[CH + ib];
    int qidxa = qa.x & 0xFFFF, qha = qa.x >> 16, npa = qa.y;
    int qidxb = qb.x & 0xFFFF, qhb = qb.x >> 16, npb = qb.y;
    int ppa = ((npa | 0x10101010) - 0x01010101) & 0x0f0f0f0f;
    int ppb = ((npb | 0x10101010) - 0x01010101) & 0x0f0f0f0f;
    __half* rowa = &g_sh[b][r][n * CH + ia][0];
    __half* rowb = &g_sh[b][r][n * CH + ib][0];
#pragma unroll
    for (int nt = 0; nt < 8; nt++) {
        int j = j0 + nt * 8 + 2 * t4;
        int4 km = *(const int4*)&kmeta[j];
        int kj0 = km.x & 0xFFFF, kh0 = km.x >> 16, kc0 = km.y;
        int kj1 = km.z & 0xFFFF, kh1 = km.z >> 16, kc1 = km.w;
        float o00 = acc[nt][0] * 0.125f, o01 = acc[nt][1] * 0.125f;
        float o10 = acc[nt][2] * 0.125f, o11 = acc[nt][3] * 0.125f;
        if (qidxa == kj0)                      o00 = -30000.0f;
        else if (qidxa < kj0 || qha != kh0)    o00 = -60000.0f;
        if (qidxa == kj1)                      o01 = -30000.0f;
        else if (qidxa < kj1 || qha != kh1)    o01 = -60000.0f;
        if (qidxb == kj0)                      o10 = -30000.0f;
        else if (qidxb < kj0 || qhb != kh0)    o10 = -60000.0f;
        if (qidxb == kj1)                      o11 = -30000.0f;
        else if (qidxb < kj1 || qhb != kh1)    o11 = -60000.0f;
        unsigned m;
        m = __vcmpeq4((unsigned)kc0, (unsigned)npa) | __vcmpeq4((unsigned)kc0, (unsigned)ppa);
        o00 -= c_log4[(__popc(m) >> 3) - 1];
        m = __vcmpeq4((unsigned)kc1, (unsigned)npa) | __vcmpeq4((unsigned)kc1, (unsigned)ppa);
        o01 -= c_log4[(__popc(m) >> 3) - 1];
        m = __vcmpeq4((unsigned)kc0, (unsigned)npb) | __vcmpeq4((unsigned)kc0, (unsigned)ppb);
        o10 -= c_log4[(__popc(m) >> 3) - 1];
        m = __vcmpeq4((unsigned)kc1, (unsigned)npb) | __vcmpeq4((unsigned)kc1, (unsigned)ppb);
        o11 -= c_log4[(__popc(m) >> 3) - 1];
        *(uint32_t*)&rowa[j] = pack2h(o00, o01);
        *(uint32_t*)&rowb[j] = pack2h(o10, o11);
    }
}

// ---------------- K4: joint softmax over fp16 scores -> fp16 p (unit layout) ----------------
__global__ void __launch_bounds__(512) k_softmax() {
    int b = blockIdx.y;
    int warp = threadIdx.x >> 5, lane = threadIdx.x & 31;
#pragma unroll 1
    for (int it = 0; it < 16; it++) {
        int l = blockIdx.x * 256 + it * 16 + warp;
        int srs[RN];
        float4 adj[RN][2];
        float mx = -3.4e38f;
#pragma unroll
        for (int r = 0; r < RN; r++) {
            srs[r] = g_oidx[b][r][l];
            const __half* srow = &g_sh[b][r][srs[r]][0];
            uint2 ua = *(const uint2*)&srow[4 * lane];        // j = 4lane..+3
            uint2 ub = *(const uint2*)&srow[128 + 4 * lane];  // j = 128+4lane..+3
            float2 a0 = unpk2h(ua.x), a1 = unpk2h(ua.y);
            float2 b0 = unpk2h(ub.x), b1 = unpk2h(ub.y);
            adj[r][0] = make_float4(a0.x, a0.y, a1.x, a1.y);
            adj[r][1] = make_float4(b0.x, b0.y, b1.x, b1.y);
#pragma unroll
            for (int h = 0; h < 2; h++) {
                mx = fmaxf(mx, fmaxf(fmaxf(adj[r][h].x, adj[r][h].y),
                                     fmaxf(adj[r][h].z, adj[r][h].w)));
            }
        }
#pragma unroll
        for (int o = 16; o; o >>= 1) mx = fmaxf(mx, __shfl_xor_sync(0xffffffffu, mx, o));
        float sum = 0.f;
#pragma unroll
        for (int r = 0; r < RN; r++)
#pragma unroll
            for (int h = 0; h < 2; h++) {
                adj[r][h].x = fexp(adj[r][h].x - mx);
                adj[r][h].y = fexp(adj[r][h].y - mx);
                adj[r][h].z = fexp(adj[r][h].z - mx);
                adj[r][h].w = fexp(adj[r][h].w - mx);
                sum += adj[r][h].x + adj[r][h].y + adj[r][h].z + adj[r][h].w;
            }
#pragma unroll
        for (int o = 16; o; o >>= 1) sum += __shfl_xor_sync(0xffffffffu, sum, o);
        float inv = 1.0f / sum;
#pragma unroll
        for (int r = 0; r < RN; r++) {
            __half* prow = &g_ph[b][r][srs[r]][0];
#pragma unroll
            for (int h = 0; h < 2; h++) {
                float4 w = adj[r][h];
                uint32_t c0 = pack2h(w.x * inv, w.y * inv);
                uint32_t c1 = pack2h(w.z * inv, w.w * inv);
                uint32_t d0 = __shfl_down_sync(0xffffffffu, c0, 2);
                uint32_t d1 = __shfl_down_sync(0xffffffffu, c1, 2);
                if ((lane & 3) < 2) {
                    int P0 = 64 * h + 2 * lane;
                    int u0 = ((P0 >> 3) << 2) + (P0 & 7);
                    *(uint4*)&prow[u0 * 4] = make_uint4(c0, d0, c1, d1);
                }
            }
        }
    }
}

// ---------------- K5: f16 mma.sync p @ v_sorted, unit-layout fragments ----------------
#define SM5_TOTAL (2 * 64 * VSTR * 2)

__global__ void __launch_bounds__(512) k_av(const float* __restrict__ v) {
    int n = blockIdx.x, r = blockIdx.y, b = blockIdx.z;
    extern __shared__ char sm5[];
    __half* vh = (__half*)sm5;
    __half* vl = vh + 64 * VSTR;
    int tid = threadIdx.x;
    int prevbase = ((n + NB2 - 1) & (NB2 - 1)) * CH;

    for (int idx = tid; idx < 128 * 16; idx += 512) {
        int P = idx & 127, f = idx >> 7;
        int ja = 2 * P, jb = ja + 1;
        int kpa = (ja < CH) ? (prevbase + ja) : (n * CH + ja - CH);
        int kpb = (jb < CH) ? (prevbase + jb) : (n * CH + jb - CH);
        int kia = g_hidx[b][r][kpa];
        int kib = g_hidx[b][r][kpb];
        float4 va = *(const float4*)&v[((size_t)b * LEN + kia) * DIM + f * 4];
        float4 vb = *(const float4*)&v[((size_t)b * LEN + kib) * DIM + f * 4];
        float pa[4] = {va.x, va.y, va.z, va.w};
        float pb[4] = {vb.x, vb.y, vb.z, vb.w};
        int t8 = P & 7;
        int off = ((P >> 3) << 4) + ((t8 & 3) << 2) + ((t8 >> 2) << 1);
#pragma unroll
        for (int c = 0; c < 4; c++) {
            uint2 s = split2h(make_float2(pa[c], pb[c]));
            *(uint32_t*)&vh[(f * 4 + c) * VSTR + off] = s.x;
            *(uint32_t*)&vl[(f * 4 + c) * VSTR + off] = s.y;
        }
    }
    __syncthreads();

    int wid = tid >> 5, lane = tid & 31;
    int wm = wid >> 1, wn = wid & 1;
    int i0 = wm * 16, d0 = wn * 32;
    int g = lane >> 2, t4 = lane & 3;

    float acc[4][4];
#pragma unroll
    for (int nt = 0; nt < 4; nt++)
#pragma unroll
        for (int c = 0; c < 4; c++) acc[nt][c] = 0.f;

    const __half* p0 = &g_ph[b][r][n * CH + i0 + g][0];
    const __half* p8 = &g_ph[b][r][n * CH + i0 + g + 8][0];
#pragma unroll 4
    for (int ks = 0; ks < 16; ks++) {
        int uoff = (ks * 4 + t4) * 4;
        uint2 ua = *(const uint2*)&p0[uoff];
        uint2 ub = *(const uint2*)&p8[uoff];
        uint32_t a[4] = {ua.x, ub.x, ua.y, ub.y};
#pragma unroll
        for (int nt = 0; nt < 4; nt++) {
            int rowb = (d0 + nt * 8 + g) * VSTR + uoff;
            uint2 bh = *(const uint2*)&vh[rowb];
            uint2 bl = *(const uint2*)&vl[rowb];
            mma_f16(acc[nt], a, bh.x, bh.y);
            mma_f16(acc[nt], a, bl.x, bl.y);
        }
    }

    int ia = i0 + g, ib = ia + 8;
#pragma unroll
    for (int nt = 0; nt < 4; nt++) {
        int d = d0 + nt * 8 + 2 * t4;
        *(float2*)&g_attn[b][r][n * CH + ia][d] = make_float2(acc[nt][0], acc[nt][1]);
        *(float2*)&g_attn[b][r][n * CH + ib][d] = make_float2(acc[nt][2], acc[nt][3]);
    }
}

// ---------------- K6: gather rounds back to original order, sum ----------------
__global__ void __launch_bounds__(256) k_out(float* __restrict__ out) {
    int gid = blockIdx.x * 256 + threadIdx.x;
    int dq = gid & 15;
    int l = (gid >> 4) & (LEN - 1);
    int b = gid >> 15;
    float4 s = make_float4(0.f, 0.f, 0.f, 0.f);
#pragma unroll
    for (int r = 0; r < RN; r++) {
        int sIdx = g_oidx[b][r][l];
        float4 a = *(const float4*)&g_attn[b][r][sIdx][dq * 4];
        s.x += a.x; s.y += a.y; s.z += a.z; s.w += a.w;
    }
    *(float4*)&out[((size_t)b * LEN + l) * DIM + dq * 4] = s;
}

// ---------------- launch ----------------
extern "C" void kernel_launch(void* const* d_in, const int* in_sizes, int n_in,
                              void* d_out, int out_size) {
    const float* q  = (const float*)d_in[0];
    const float* v  = (const float*)d_in[1];
    const float* rm = (const float*)d_in[2];
    float* out = (float*)d_out;

    cudaFuncSetAttribute(k_scores, cudaFuncAttributeMaxDynamicSharedMemorySize, SM3_TOTAL);
    cudaFuncSetAttribute(k_av,     cudaFuncAttributeMaxDynamicSharedMemorySize, SM5_TOTAL);

    k_rmn<<<BHN, 64>>>(rm);
    k_hash<<<dim3(LEN / 128, BHN), 128>>>(q);
    k_sort<<<BHN * RN, 256>>>();
    k_scores<<<dim3(NB2, RN, BHN), 1024, SM3_TOTAL>>>();   // launch #3 -> ncu slot
    k_softmax<<<dim3(LEN / 256, BHN), 512>>>();
    k_av<<<dim3(NB2, RN, BHN), 512, SM5_TOTAL>>>(v);
    k_out<<<(BHN * LEN * 16) / 256, 256>>>(out);
}